// round 4
// baseline (speedup 1.0000x reference)
#include <cuda_runtime.h>
#include <cstdint>

// Problem dims
#define BB 256
#define NN 768
#define HH 3072
#define LL 19

// Fixed CSR/CSC capacities (construction: W_vn<=3, masks<=7, W_out<=4, bm/S/cm cols = 1)
#define CAP_W 4
#define CAP_M 8
#define CAP_O 4
#define CAP_B 2
#define CAP_S 2
#define CAP_C 2

// ---------------- device scratch (no allocation allowed) ----------------
__device__ __align__(16) uint16_t g_w_idx [LL * HH * CAP_W];
__device__ __align__(16) float    g_w_val [LL * HH * CAP_W];
__device__ __align__(16) uint16_t g_mf_idx[HH * CAP_M];
__device__ __align__(16) uint16_t g_mc_idx[HH * CAP_M];
__device__ __align__(16) uint16_t g_wo_idx[NN * CAP_O];
__device__ __align__(16) float    g_wo_val[NN * CAP_O];
__device__ __align__(16) uint16_t g_bm_idx[HH * CAP_B];
__device__ __align__(16) float    g_bm_val[HH * CAP_B];
__device__ __align__(16) uint16_t g_s_idx [20 * NN * CAP_S];
__device__ __align__(16) float    g_s_val [20 * NN * CAP_S];
__device__ __align__(16) uint16_t g_cm_idx[NN * CAP_C];
__device__ __align__(16) float    g_cm_val[NN * CAP_C];

// ---------------- sparsity extraction: ballot fast-path scan ----------------
// Warp-per-row. Each iteration a warp reads 512 contiguous bytes (LDG.128/lane).
// Zero chunks (the overwhelming majority: <=7 nnz per row) cost only the load,
// an integer OR-tree zero test, and one ballot — no loop-carried SHFL chain.
// Nonzero chunks compact via ballot+popc (order within a row is irrelevant:
// the slots feed a symmetric dot-product / masked-product).
// bits<<1 zero test treats -0.0f as zero, matching the reference's (x != 0).
template<int C, int CAP, bool ISMASK, int SENT>
__device__ __forceinline__ void row_scan_fast(const float* __restrict__ M, int R,
                                              uint16_t* __restrict__ idx,
                                              float* __restrict__ val)
{
    int row  = (blockIdx.x * blockDim.x + threadIdx.x) >> 5;
    int lane = threadIdx.x & 31;
    if (row >= R) return;
    const float4* rp = reinterpret_cast<const float4*>(M + (size_t)row * C);
    uint16_t* oi = idx + (size_t)row * CAP;
    float*    ov = ISMASK ? nullptr : (val + (size_t)row * CAP);
    constexpr int ITER = C / 128;          // 512B warp-chunks per row (24 or 6)
    int base = 0;
    #pragma unroll 4
    for (int it = 0; it < ITER; it++) {
        float4 v = __ldcs(rp + it * 32 + lane);
        unsigned a0 = __float_as_uint(v.x) << 1;
        unsigned a1 = __float_as_uint(v.y) << 1;
        unsigned a2 = __float_as_uint(v.z) << 1;
        unsigned a3 = __float_as_uint(v.w) << 1;
        unsigned any  = a0 | a1 | a2 | a3;
        unsigned ball = __ballot_sync(0xffffffffu, any != 0u);
        if (ball) {                         // warp-uniform, rare
            unsigned b0 = __ballot_sync(0xffffffffu, a0 != 0u);
            unsigned b1 = __ballot_sync(0xffffffffu, a1 != 0u);
            unsigned b2 = __ballot_sync(0xffffffffu, a2 != 0u);
            unsigned b3 = __ballot_sync(0xffffffffu, a3 != 0u);
            unsigned lb = (1u << lane) - 1u;
            int c0 = __popc(b0), c1 = __popc(b1), c2 = __popc(b2), c3 = __popc(b3);
            int col = (it * 32 + lane) * 4;
            int p;
            if (a0) { p = base + __popc(b0 & lb);
                      if (p < CAP) { oi[p] = (uint16_t)col;       if (!ISMASK) ov[p] = v.x; } }
            if (a1) { p = base + c0 + __popc(b1 & lb);
                      if (p < CAP) { oi[p] = (uint16_t)(col + 1); if (!ISMASK) ov[p] = v.y; } }
            if (a2) { p = base + c0 + c1 + __popc(b2 & lb);
                      if (p < CAP) { oi[p] = (uint16_t)(col + 2); if (!ISMASK) ov[p] = v.z; } }
            if (a3) { p = base + c0 + c1 + c2 + __popc(b3 & lb);
                      if (p < CAP) { oi[p] = (uint16_t)(col + 3); if (!ISMASK) ov[p] = v.w; } }
            base += c0 + c1 + c2 + c3;
        }
    }
    if (base > CAP) base = CAP;
    for (int p = base + lane; p < CAP; p += 32) {
        oi[p] = (uint16_t)SENT;
        if (!ISMASK) ov[p] = 0.0f;
    }
}

// Thread-per-column scan (coalesced across the warp each row step).
template<int CAPT>
__device__ __forceinline__ void col_scan(const float* __restrict__ M, int R, int C,
                                         uint16_t* __restrict__ idx, float* __restrict__ val)
{
    int col = blockIdx.x * blockDim.x + threadIdx.x;
    int sl  = blockIdx.y;
    if (col >= C) return;
    const float* p = M + (size_t)sl * R * C;
    uint16_t* oi = idx + ((size_t)sl * C + col) * CAPT;
    float*    ov = val + ((size_t)sl * C + col) * CAPT;
    int cnt = 0;
    #pragma unroll 8
    for (int r = 0; r < R; r++) {
        float v = __ldcs(&p[(size_t)r * C + col]);
        if (v != 0.0f && cnt < CAPT) { oi[cnt] = (uint16_t)r; ov[cnt] = v; cnt++; }
    }
    for (; cnt < CAPT; cnt++) { oi[cnt] = 0; ov[cnt] = 0.0f; }
}

__global__ void k_wvn (const float* __restrict__ M){ row_scan_fast<HH, CAP_W, false, 0 >(M, LL*HH, g_w_idx,  g_w_val); }
__global__ void k_wout(const float* __restrict__ M){ row_scan_fast<HH, CAP_O, false, 0 >(M, NN,    g_wo_idx, g_wo_val); }
__global__ void k_mf  (const float* __restrict__ M){ row_scan_fast<NN, CAP_M, true,  NN>(M, HH,    g_mf_idx, nullptr); }
__global__ void k_mc  (const float* __restrict__ M){ row_scan_fast<HH, CAP_M, true,  HH>(M, HH,    g_mc_idx, nullptr); }
__global__ void k_bm  (const float* __restrict__ M){ col_scan<CAP_B>(M, NN, HH, g_bm_idx, g_bm_val); }
__global__ void k_s   (const float* __restrict__ M){ col_scan<CAP_S>(M, NN, NN, g_s_idx,  g_s_val);  }
__global__ void k_cm  (const float* __restrict__ M){ col_scan<CAP_C>(M, NN, NN, g_cm_idx, g_cm_val); }

// ---------------- math helpers (fast MUFU intrinsics, ~1e-7 rel err) ----------------
__device__ __forceinline__ float fast_tanh_half(float z)   // tanh(z/2)
{
    float e = __expf(-fabsf(z));
    float r = __fdividef(1.0f - e, 1.0f + e);
    return copysignf(r, z);
}
__device__ __forceinline__ float two_atanh_clip(float t)   // 2*atanh(clip(t))
{
    t = fminf(fmaxf(t, -0.999999f), 0.999999f);
    return __logf(__fdividef(1.0f + t, 1.0f - t));
}
// Product of nonzero gathered entries; 0 if all zero. Sentinel slots hold 0.
__device__ __forceinline__ float cn_prod8(uint4 q, const float* __restrict__ buf)
{
    int i0 = q.x & 0xffff, i1 = q.x >> 16;
    int i2 = q.y & 0xffff, i3 = q.y >> 16;
    int i4 = q.z & 0xffff, i5 = q.z >> 16;
    int i6 = q.w & 0xffff, i7 = q.w >> 16;
    float p = 1.0f; int any = 0; float v; bool nz;
    v = buf[i0]; nz = (v != 0.0f); any |= nz; p *= nz ? v : 1.0f;
    v = buf[i1]; nz = (v != 0.0f); any |= nz; p *= nz ? v : 1.0f;
    v = buf[i2]; nz = (v != 0.0f); any |= nz; p *= nz ? v : 1.0f;
    v = buf[i3]; nz = (v != 0.0f); any |= nz; p *= nz ? v : 1.0f;
    v = buf[i4]; nz = (v != 0.0f); any |= nz; p *= nz ? v : 1.0f;
    v = buf[i5]; nz = (v != 0.0f); any |= nz; p *= nz ? v : 1.0f;
    v = buf[i6]; nz = (v != 0.0f); any |= nz; p *= nz ? v : 1.0f;
    v = buf[i7]; nz = (v != 0.0f); any |= nz; p *= nz ? v : 1.0f;
    return any ? p : 0.0f;
}

// ---------------- the whole network, fused: one block per batch element ----------------
__global__ void __launch_bounds__(256, 2) bp_main(const float* __restrict__ x,
                                                  float* __restrict__ out)
{
    __shared__ float bufA[HH + 4], bufB[HH + 4], xrow[NN], ybuf[NN + 4];
    const int t = threadIdx.x;
    const int b = blockIdx.x;

    if (t == 0) { bufA[HH] = 0.0f; bufB[HH] = 0.0f; ybuf[NN] = 0.0f; }  // sentinel slots
    for (int n = t; n < NN; n += 256) xrow[n] = x[(size_t)b * NN + n];
    __syncthreads();

    // stage 0: t = tanh(0.5 x) (into ybuf), then h = CN(M_first, t)
    for (int n = t; n < NN; n += 256) ybuf[n] = fast_tanh_half(xrow[n]);
    __syncthreads();
    {
        const uint4* mf = reinterpret_cast<const uint4*>(g_mf_idx);
        for (int i = t; i < HH; i += 256) bufA[i] = cn_prod8(mf[i], ybuf);
    }
    __syncthreads();

    float* hb = bufA;
    float* ub = bufB;
    const uint4*    mc4 = reinterpret_cast<const uint4*>(g_mc_idx);
    const uint2*    wi2 = reinterpret_cast<const uint2*>(g_w_idx);
    const float4*   wv4 = reinterpret_cast<const float4*>(g_w_val);
    const uint32_t* bmi = reinterpret_cast<const uint32_t*>(g_bm_idx);
    const float2*   bmv = reinterpret_cast<const float2*>(g_bm_val);
    const uint32_t* si  = reinterpret_cast<const uint32_t*>(g_s_idx);
    const float2*   sv  = reinterpret_cast<const float2*>(g_s_val);

    for (int l = 0; l < LL; l++) {
        // u = 2*atanh(clip(h));  y = x @ S[l]
        for (int j = t; j < HH; j += 256) ub[j] = two_atanh_clip(hb[j]);
        for (int m = t; m < NN; m += 256) {
            uint32_t q = si[l * NN + m]; float2 w = sv[l * NN + m];
            ybuf[m] = w.x * xrow[q & 0xffff] + w.y * xrow[q >> 16];
        }
        __syncthreads();
        // v = tanh(0.5*(W u + bias_gather(y)))
        for (int i = t; i < HH; i += 256) {
            uint32_t bq = bmi[i]; float2 bw = bmv[i];
            float z = bw.x * ybuf[bq & 0xffff] + bw.y * ybuf[bq >> 16];
            uint2 wq = wi2[l * HH + i]; float4 ww = wv4[l * HH + i];
            z += ww.x * ub[wq.x & 0xffff];
            z += ww.y * ub[wq.x >> 16];
            z += ww.z * ub[wq.y & 0xffff];
            z += ww.w * ub[wq.y >> 16];
            hb[i] = fast_tanh_half(z);
        }
        __syncthreads();
        // h' = CN(M_cn, v)
        for (int i = t; i < HH; i += 256) ub[i] = cn_prod8(mc4[i], hb);
        __syncthreads();
        float* tmp = hb; hb = ub; ub = tmp;
    }

    // output layer
    for (int j = t; j < HH; j += 256) ub[j] = two_atanh_clip(hb[j]);
    for (int m = t; m < NN; m += 256) {
        uint32_t q = si[19 * NN + m]; float2 w = sv[19 * NN + m];
        ybuf[m] = w.x * xrow[q & 0xffff] + w.y * xrow[q >> 16];
    }
    __syncthreads();
    {
        const uint2*    oi2 = reinterpret_cast<const uint2*>(g_wo_idx);
        const float4*   ov4 = reinterpret_cast<const float4*>(g_wo_val);
        const uint32_t* cmi = reinterpret_cast<const uint32_t*>(g_cm_idx);
        const float2*   cmv = reinterpret_cast<const float2*>(g_cm_val);
        for (int n = t; n < NN; n += 256) {
            uint32_t cq = cmi[n]; float2 cw = cmv[n];
            float s = cw.x * ybuf[cq & 0xffff] + cw.y * ybuf[cq >> 16];
            uint2 wq = oi2[n]; float4 ww = ov4[n];
            s += ww.x * ub[wq.x & 0xffff];
            s += ww.y * ub[wq.x >> 16];
            s += ww.z * ub[wq.y & 0xffff];
            s += ww.w * ub[wq.y >> 16];
            out[(size_t)b * NN + n] = __fdividef(1.0f, 1.0f + __expf(-s));
        }
    }
}

// ---------------- launch ----------------
extern "C" void kernel_launch(void* const* d_in, const int* in_sizes, int n_in,
                              void* d_out, int out_size)
{
    (void)in_sizes; (void)n_in; (void)out_size;
    const float* x    = (const float*)d_in[0];   // [256, 768]
    const float* Wvn  = (const float*)d_in[1];   // [19, 3072, 3072]
    const float* Wout = (const float*)d_in[2];   // [768, 3072]
    const float* S    = (const float*)d_in[3];   // [20, 768, 768]
    const float* bm   = (const float*)d_in[4];   // [768, 3072]
    const float* cm   = (const float*)d_in[5];   // [768, 768]
    const float* Mf   = (const float*)d_in[6];   // [3072, 768]
    const float* Mc   = (const float*)d_in[7];   // [3072, 3072]
    float* out = (float*)d_out;                  // [256, 768]

    // Sparsity extraction (8 warps/block -> 8 rows/block for row scans)
    k_wvn <<<(LL * HH + 7) / 8, 256>>>(Wvn);
    k_wout<<<(NN + 7) / 8,      256>>>(Wout);
    k_mf  <<<(HH + 7) / 8,      256>>>(Mf);
    k_mc  <<<(HH + 7) / 8,      256>>>(Mc);
    k_bm  <<<dim3((HH + 255) / 256, 1),  256>>>(bm);
    k_s   <<<dim3((NN + 255) / 256, 20), 256>>>(S);
    k_cm  <<<dim3((NN + 255) / 256, 1),  256>>>(cm);

    // Fused BP network: one block per batch element
    bp_main<<<BB, 256>>>(x, out);
}

// round 8
// speedup vs baseline: 2.6004x; 2.6004x over previous
#include <cuda_runtime.h>
#include <cstdint>

// Problem dims
#define BB 256
#define NN 768
#define HH 3072
#define LL 19

// Fixed CSR/CSC capacities (construction: W_vn<=3, masks<=7, W_out<=4, bm/S/cm cols = 1)
#define CAP_W 4
#define CAP_M 8
#define CAP_O 4
#define CAP_B 2
#define CAP_S 2
#define CAP_C 2

// ---------------- device scratch (no allocation allowed) ----------------
__device__ __align__(16) uint16_t g_w_idx [LL * HH * CAP_W];
__device__ __align__(16) float    g_w_val [LL * HH * CAP_W];
__device__ __align__(16) uint16_t g_mf_idx[HH * CAP_M];
__device__ __align__(16) uint16_t g_mc_idx[HH * CAP_M];
__device__ __align__(16) uint16_t g_wo_idx[NN * CAP_O];
__device__ __align__(16) float    g_wo_val[NN * CAP_O];
__device__ __align__(16) uint16_t g_bm_idx[HH * CAP_B];
__device__ __align__(16) float    g_bm_val[HH * CAP_B];
__device__ __align__(16) uint16_t g_s_idx [20 * NN * CAP_S];
__device__ __align__(16) float    g_s_val [20 * NN * CAP_S];
__device__ __align__(16) uint16_t g_cm_idx[NN * CAP_C];
__device__ __align__(16) float    g_cm_val[NN * CAP_C];

// ---------------- sparsity extraction ----------------
// Warp-per-row. The inner loop has NO cross-lane ops and NO loop-carried
// dependency: every LDG.128 is independent, so ptxas front-batches loads
// (high MLP). Each lane privately captures its hits (rare: <=3 or <=7 per
// whole row) into a small register list via a rarely-taken per-thread branch.
// Warp-level compaction (shfl prefix over per-lane counts + scatter) runs
// ONCE per row. Output slot order within a row is lane-major, which is fine:
// the consumers are order-invariant (sum / product).
// Zero test uses bits<<1 so -0.0f counts as zero, matching (x != 0).
template<int C, int CAP, int PCAP, bool ISMASK, int SENT>
__device__ __forceinline__ void row_scan(const float* __restrict__ M, int R,
                                         uint16_t* __restrict__ idx,
                                         float* __restrict__ val)
{
    int row  = (blockIdx.x * blockDim.x + threadIdx.x) >> 5;
    int lane = threadIdx.x & 31;
    if (row >= R) return;
    const float4* rp = reinterpret_cast<const float4*>(M + (size_t)row * C) + lane;

    int   li[PCAP];
    float lv[PCAP];
    int cnt = 0;

    constexpr int ITER = C / 128;   // 512B warp-chunks per row (24 or 6)
    #pragma unroll 8
    for (int it = 0; it < ITER; it++) {
        float4 v = rp[it * 32];
        unsigned a0 = __float_as_uint(v.x) << 1;
        unsigned a1 = __float_as_uint(v.y) << 1;
        unsigned a2 = __float_as_uint(v.z) << 1;
        unsigned a3 = __float_as_uint(v.w) << 1;
        if ((a0 | a1 | a2 | a3) != 0u) {          // per-thread branch, rarely taken
            int col = (it * 32 + lane) * 4;
            #pragma unroll
            for (int e = 0; e < 4; e++) {
                unsigned ae = (e == 0) ? a0 : (e == 1) ? a1 : (e == 2) ? a2 : a3;
                float    ve = (e == 0) ? v.x : (e == 1) ? v.y : (e == 2) ? v.z : v.w;
                if (ae != 0u) {
                    #pragma unroll
                    for (int k = 0; k < PCAP; k++)
                        if (cnt == k) { li[k] = col + e; lv[k] = ve; }
                    if (cnt < PCAP) cnt++;
                }
            }
        }
    }

    // Once-per-row warp compaction
    int pre = cnt;
    #pragma unroll
    for (int d = 1; d < 32; d <<= 1) {
        int o = __shfl_up_sync(0xffffffffu, pre, d);
        if (lane >= d) pre += o;
    }
    int total = __shfl_sync(0xffffffffu, pre, 31);
    int base  = pre - cnt;   // exclusive prefix

    uint16_t* oi = idx + (size_t)row * CAP;
    float*    ov = ISMASK ? nullptr : (val + (size_t)row * CAP);
    #pragma unroll
    for (int k = 0; k < PCAP; k++) {
        if (k < cnt) {
            int p = base + k;
            if (p < CAP) { oi[p] = (uint16_t)li[k]; if (!ISMASK) ov[p] = lv[k]; }
        }
    }
    if (total > CAP) total = CAP;
    for (int p = total + lane; p < CAP; p += 32) {
        oi[p] = (uint16_t)SENT;
        if (!ISMASK) ov[p] = 0.0f;
    }
}

// Thread-per-column scan (reads coalesced across the warp each row step).
template<int CAPT>
__device__ __forceinline__ void col_scan(const float* __restrict__ M, int R, int C,
                                         uint16_t* __restrict__ idx, float* __restrict__ val)
{
    int col = blockIdx.x * blockDim.x + threadIdx.x;
    int sl  = blockIdx.y;
    if (col >= C) return;
    const float* p = M + (size_t)sl * R * C;
    uint16_t* oi = idx + ((size_t)sl * C + col) * CAPT;
    float*    ov = val + ((size_t)sl * C + col) * CAPT;
    int cnt = 0;
    #pragma unroll 8
    for (int r = 0; r < R; r++) {
        float v = p[(size_t)r * C + col];
        if (v != 0.0f && cnt < CAPT) { oi[cnt] = (uint16_t)r; ov[cnt] = v; cnt++; }
    }
    for (; cnt < CAPT; cnt++) { oi[cnt] = 0; ov[cnt] = 0.0f; }
}

__global__ void k_wvn (const float* __restrict__ M){ row_scan<HH, CAP_W, 4, false, 0 >(M, LL*HH, g_w_idx,  g_w_val); }
__global__ void k_wout(const float* __restrict__ M){ row_scan<HH, CAP_O, 4, false, 0 >(M, NN,    g_wo_idx, g_wo_val); }
__global__ void k_mf  (const float* __restrict__ M){ row_scan<NN, CAP_M, 8, true,  NN>(M, HH,    g_mf_idx, nullptr); }
__global__ void k_mc  (const float* __restrict__ M){ row_scan<HH, CAP_M, 8, true,  HH>(M, HH,    g_mc_idx, nullptr); }
__global__ void k_bm  (const float* __restrict__ M){ col_scan<CAP_B>(M, NN, HH, g_bm_idx, g_bm_val); }
__global__ void k_s   (const float* __restrict__ M){ col_scan<CAP_S>(M, NN, NN, g_s_idx,  g_s_val);  }
__global__ void k_cm  (const float* __restrict__ M){ col_scan<CAP_C>(M, NN, NN, g_cm_idx, g_cm_val); }

// ---------------- math helpers (fast MUFU intrinsics, ~1e-7 rel err) ----------------
__device__ __forceinline__ float fast_tanh_half(float z)   // tanh(z/2)
{
    float e = __expf(-fabsf(z));
    float r = __fdividef(1.0f - e, 1.0f + e);
    return copysignf(r, z);
}
__device__ __forceinline__ float two_atanh_clip(float t)   // 2*atanh(clip(t))
{
    t = fminf(fmaxf(t, -0.999999f), 0.999999f);
    return __logf(__fdividef(1.0f + t, 1.0f - t));
}
// Product of nonzero gathered entries; 0 if all zero. Sentinel slots hold 0.
__device__ __forceinline__ float cn_prod8(uint4 q, const float* __restrict__ buf)
{
    int i0 = q.x & 0xffff, i1 = q.x >> 16;
    int i2 = q.y & 0xffff, i3 = q.y >> 16;
    int i4 = q.z & 0xffff, i5 = q.z >> 16;
    int i6 = q.w & 0xffff, i7 = q.w >> 16;
    float p = 1.0f; int any = 0; float v; bool nz;
    v = buf[i0]; nz = (v != 0.0f); any |= nz; p *= nz ? v : 1.0f;
    v = buf[i1]; nz = (v != 0.0f); any |= nz; p *= nz ? v : 1.0f;
    v = buf[i2]; nz = (v != 0.0f); any |= nz; p *= nz ? v : 1.0f;
    v = buf[i3]; nz = (v != 0.0f); any |= nz; p *= nz ? v : 1.0f;
    v = buf[i4]; nz = (v != 0.0f); any |= nz; p *= nz ? v : 1.0f;
    v = buf[i5]; nz = (v != 0.0f); any |= nz; p *= nz ? v : 1.0f;
    v = buf[i6]; nz = (v != 0.0f); any |= nz; p *= nz ? v : 1.0f;
    v = buf[i7]; nz = (v != 0.0f); any |= nz; p *= nz ? v : 1.0f;
    return any ? p : 0.0f;
}

// ---------------- the whole network, fused: one block per batch element ----------------
__global__ void __launch_bounds__(256, 2) bp_main(const float* __restrict__ x,
                                                  float* __restrict__ out)
{
    __shared__ float bufA[HH + 4], bufB[HH + 4], xrow[NN], ybuf[NN + 4];
    const int t = threadIdx.x;
    const int b = blockIdx.x;

    if (t == 0) { bufA[HH] = 0.0f; bufB[HH] = 0.0f; ybuf[NN] = 0.0f; }  // sentinel slots
    for (int n = t; n < NN; n += 256) xrow[n] = x[(size_t)b * NN + n];
    __syncthreads();

    // stage 0: t = tanh(0.5 x) (into ybuf), then h = CN(M_first, t)
    for (int n = t; n < NN; n += 256) ybuf[n] = fast_tanh_half(xrow[n]);
    __syncthreads();
    {
        const uint4* mf = reinterpret_cast<const uint4*>(g_mf_idx);
        for (int i = t; i < HH; i += 256) bufA[i] = cn_prod8(mf[i], ybuf);
    }
    __syncthreads();

    float* hb = bufA;
    float* ub = bufB;
    const uint4*    mc4 = reinterpret_cast<const uint4*>(g_mc_idx);
    const uint2*    wi2 = reinterpret_cast<const uint2*>(g_w_idx);
    const float4*   wv4 = reinterpret_cast<const float4*>(g_w_val);
    const uint32_t* bmi = reinterpret_cast<const uint32_t*>(g_bm_idx);
    const float2*   bmv = reinterpret_cast<const float2*>(g_bm_val);
    const uint32_t* si  = reinterpret_cast<const uint32_t*>(g_s_idx);
    const float2*   sv  = reinterpret_cast<const float2*>(g_s_val);

    for (int l = 0; l < LL; l++) {
        // u = 2*atanh(clip(h));  y = x @ S[l]
        for (int j = t; j < HH; j += 256) ub[j] = two_atanh_clip(hb[j]);
        for (int m = t; m < NN; m += 256) {
            uint32_t q = si[l * NN + m]; float2 w = sv[l * NN + m];
            ybuf[m] = w.x * xrow[q & 0xffff] + w.y * xrow[q >> 16];
        }
        __syncthreads();
        // v = tanh(0.5*(W u + bias_gather(y)))
        for (int i = t; i < HH; i += 256) {
            uint32_t bq = bmi[i]; float2 bw = bmv[i];
            float z = bw.x * ybuf[bq & 0xffff] + bw.y * ybuf[bq >> 16];
            uint2 wq = wi2[l * HH + i]; float4 ww = wv4[l * HH + i];
            z += ww.x * ub[wq.x & 0xffff];
            z += ww.y * ub[wq.x >> 16];
            z += ww.z * ub[wq.y & 0xffff];
            z += ww.w * ub[wq.y >> 16];
            hb[i] = fast_tanh_half(z);
        }
        __syncthreads();
        // h' = CN(M_cn, v)
        for (int i = t; i < HH; i += 256) ub[i] = cn_prod8(mc4[i], hb);
        __syncthreads();
        float* tmp = hb; hb = ub; ub = tmp;
    }

    // output layer
    for (int j = t; j < HH; j += 256) ub[j] = two_atanh_clip(hb[j]);
    for (int m = t; m < NN; m += 256) {
        uint32_t q = si[19 * NN + m]; float2 w = sv[19 * NN + m];
        ybuf[m] = w.x * xrow[q & 0xffff] + w.y * xrow[q >> 16];
    }
    __syncthreads();
    {
        const uint2*    oi2 = reinterpret_cast<const uint2*>(g_wo_idx);
        const float4*   ov4 = reinterpret_cast<const float4*>(g_wo_val);
        const uint32_t* cmi = reinterpret_cast<const uint32_t*>(g_cm_idx);
        const float2*   cmv = reinterpret_cast<const float2*>(g_cm_val);
        for (int n = t; n < NN; n += 256) {
            uint32_t cq = cmi[n]; float2 cw = cmv[n];
            float s = cw.x * ybuf[cq & 0xffff] + cw.y * ybuf[cq >> 16];
            uint2 wq = oi2[n]; float4 ww = ov4[n];
            s += ww.x * ub[wq.x & 0xffff];
            s += ww.y * ub[wq.x >> 16];
            s += ww.z * ub[wq.y & 0xffff];
            s += ww.w * ub[wq.y >> 16];
            out[(size_t)b * NN + n] = __fdividef(1.0f, 1.0f + __expf(-s));
        }
    }
}

// ---------------- launch ----------------
extern "C" void kernel_launch(void* const* d_in, const int* in_sizes, int n_in,
                              void* d_out, int out_size)
{
    (void)in_sizes; (void)n_in; (void)out_size;
    const float* x    = (const float*)d_in[0];   // [256, 768]
    const float* Wvn  = (const float*)d_in[1];   // [19, 3072, 3072]
    const float* Wout = (const float*)d_in[2];   // [768, 3072]
    const float* S    = (const float*)d_in[3];   // [20, 768, 768]
    const float* bm   = (const float*)d_in[4];   // [768, 3072]
    const float* cm   = (const float*)d_in[5];   // [768, 768]
    const float* Mf   = (const float*)d_in[6];   // [3072, 768]
    const float* Mc   = (const float*)d_in[7];   // [3072, 3072]
    float* out = (float*)d_out;                  // [256, 768]

    // Sparsity extraction (8 warps/block -> 8 rows/block for row scans)
    k_wvn <<<(LL * HH + 7) / 8, 256>>>(Wvn);
    k_wout<<<(NN + 7) / 8,      256>>>(Wout);
    k_mf  <<<(HH + 7) / 8,      256>>>(Mf);
    k_mc  <<<(HH + 7) / 8,      256>>>(Mc);
    k_bm  <<<dim3((HH + 255) / 256, 1),  256>>>(bm);
    k_s   <<<dim3((NN + 255) / 256, 20), 256>>>(S);
    k_cm  <<<dim3((NN + 255) / 256, 1),  256>>>(cm);

    // Fused BP network: one block per batch element
    bp_main<<<BB, 256>>>(x, out);
}

// round 11
// speedup vs baseline: 2.7529x; 1.0586x over previous
#include <cuda_runtime.h>
#include <cstdint>

// Problem dims
#define BB 256
#define NN 768
#define HH 3072
#define LL 19

// Fixed CSR/CSC capacities (construction: W_vn<=3, masks<=7, W_out<=4, bm/S/cm cols = 1)
#define CAP_W 4
#define CAP_M 8
#define CAP_O 4
#define CAP_B 2
#define CAP_S 2
#define CAP_C 2

// ---------------- device scratch (no allocation allowed) ----------------
__device__ __align__(16) uint16_t g_w_idx [LL * HH * CAP_W];
__device__ __align__(16) float    g_w_val [LL * HH * CAP_W];
__device__ __align__(16) uint16_t g_mf_idx[HH * CAP_M];
__device__ __align__(16) uint16_t g_mc_idx[HH * CAP_M];
__device__ __align__(16) uint16_t g_wo_idx[NN * CAP_O];
__device__ __align__(16) float    g_wo_val[NN * CAP_O];
__device__ __align__(16) uint16_t g_bm_idx[HH * CAP_B];
__device__ __align__(16) float    g_bm_val[HH * CAP_B];
__device__ __align__(16) uint16_t g_s_idx [20 * NN * CAP_S];
__device__ __align__(16) float    g_s_val [20 * NN * CAP_S];
__device__ __align__(16) uint16_t g_cm_idx[NN * CAP_C];
__device__ __align__(16) float    g_cm_val[NN * CAP_C];

// ---------------- sparsity extraction ----------------
// Warp-per-row, two-phase batched loop. Phase 1 loads NB float4 chunks into an
// explicit register array with NO intervening branches -> ptxas must front-batch
// them (MLP = NB, guaranteed by structure). Phase 2 runs the zero-test /
// capture over registers. Hits are captured per-lane into a tiny register list
// (rare: <=3 / <=7 per whole row); warp compaction (shfl prefix + scatter)
// runs ONCE per row. Slot order is lane-major, fine for the order-invariant
// consumers (sum / product).
// Zero test uses bits<<1 so -0.0f counts as zero, matching (x != 0).
template<int C, int CAP, int PCAP, bool ISMASK, int SENT>
__device__ __forceinline__ void row_scan(const float* __restrict__ M, int R,
                                         uint16_t* __restrict__ idx,
                                         float* __restrict__ val)
{
    int row  = (blockIdx.x * blockDim.x + threadIdx.x) >> 5;
    int lane = threadIdx.x & 31;
    if (row >= R) return;
    const float4* rp = reinterpret_cast<const float4*>(M + (size_t)row * C) + lane;

    int   li[PCAP];
    float lv[PCAP];
    int cnt = 0;

    constexpr int ITER = C / 128;                 // 512B warp-chunks per row (24 or 6)
    constexpr int NB   = (ITER < 8) ? ITER : 8;   // load batch size (MLP)
    static_assert(ITER % NB == 0, "batch must divide row chunks");

    for (int it0 = 0; it0 < ITER; it0 += NB) {
        // Phase 1: batched loads, no branches between them (forces MLP = NB)
        float4 v[NB];
        #pragma unroll
        for (int u = 0; u < NB; u++) v[u] = rp[(it0 + u) * 32];

        // Phase 2: zero-test + rare capture, all in registers
        #pragma unroll
        for (int u = 0; u < NB; u++) {
            unsigned a0 = __float_as_uint(v[u].x) << 1;
            unsigned a1 = __float_as_uint(v[u].y) << 1;
            unsigned a2 = __float_as_uint(v[u].z) << 1;
            unsigned a3 = __float_as_uint(v[u].w) << 1;
            if ((a0 | a1 | a2 | a3) != 0u) {      // per-thread branch, rarely taken
                int col = ((it0 + u) * 32 + lane) * 4;
                #pragma unroll
                for (int e = 0; e < 4; e++) {
                    unsigned ae = (e == 0) ? a0 : (e == 1) ? a1 : (e == 2) ? a2 : a3;
                    float    ve = (e == 0) ? v[u].x : (e == 1) ? v[u].y
                                : (e == 2) ? v[u].z : v[u].w;
                    if (ae != 0u) {
                        #pragma unroll
                        for (int k = 0; k < PCAP; k++)
                            if (cnt == k) { li[k] = col + e; lv[k] = ve; }
                        if (cnt < PCAP) cnt++;
                    }
                }
            }
        }
    }

    // Once-per-row warp compaction
    int pre = cnt;
    #pragma unroll
    for (int d = 1; d < 32; d <<= 1) {
        int o = __shfl_up_sync(0xffffffffu, pre, d);
        if (lane >= d) pre += o;
    }
    int total = __shfl_sync(0xffffffffu, pre, 31);
    int base  = pre - cnt;   // exclusive prefix

    uint16_t* oi = idx + (size_t)row * CAP;
    float*    ov = ISMASK ? nullptr : (val + (size_t)row * CAP);
    #pragma unroll
    for (int k = 0; k < PCAP; k++) {
        if (k < cnt) {
            int p = base + k;
            if (p < CAP) { oi[p] = (uint16_t)li[k]; if (!ISMASK) ov[p] = lv[k]; }
        }
    }
    if (total > CAP) total = CAP;
    for (int p = total + lane; p < CAP; p += 32) {
        oi[p] = (uint16_t)SENT;
        if (!ISMASK) ov[p] = 0.0f;
    }
}

// Thread-per-column scan (reads coalesced across the warp each row step).
template<int CAPT>
__device__ __forceinline__ void col_scan(const float* __restrict__ M, int R, int C,
                                         uint16_t* __restrict__ idx, float* __restrict__ val)
{
    int col = blockIdx.x * blockDim.x + threadIdx.x;
    int sl  = blockIdx.y;
    if (col >= C) return;
    const float* p = M + (size_t)sl * R * C;
    uint16_t* oi = idx + ((size_t)sl * C + col) * CAPT;
    float*    ov = val + ((size_t)sl * C + col) * CAPT;
    int cnt = 0;
    #pragma unroll 8
    for (int r = 0; r < R; r++) {
        float v = p[(size_t)r * C + col];
        if (v != 0.0f && cnt < CAPT) { oi[cnt] = (uint16_t)r; ov[cnt] = v; cnt++; }
    }
    for (; cnt < CAPT; cnt++) { oi[cnt] = 0; ov[cnt] = 0.0f; }
}

__global__ void __launch_bounds__(256) k_wvn (const float* __restrict__ M){ row_scan<HH, CAP_W, 4, false, 0 >(M, LL*HH, g_w_idx,  g_w_val); }
__global__ void __launch_bounds__(256) k_wout(const float* __restrict__ M){ row_scan<HH, CAP_O, 4, false, 0 >(M, NN,    g_wo_idx, g_wo_val); }
__global__ void __launch_bounds__(256) k_mf  (const float* __restrict__ M){ row_scan<NN, CAP_M, 8, true,  NN>(M, HH,    g_mf_idx, nullptr); }
__global__ void __launch_bounds__(256) k_mc  (const float* __restrict__ M){ row_scan<HH, CAP_M, 8, true,  HH>(M, HH,    g_mc_idx, nullptr); }
__global__ void __launch_bounds__(256) k_bm  (const float* __restrict__ M){ col_scan<CAP_B>(M, NN, HH, g_bm_idx, g_bm_val); }
__global__ void __launch_bounds__(256) k_s   (const float* __restrict__ M){ col_scan<CAP_S>(M, NN, NN, g_s_idx,  g_s_val);  }
__global__ void __launch_bounds__(256) k_cm  (const float* __restrict__ M){ col_scan<CAP_C>(M, NN, NN, g_cm_idx, g_cm_val); }

// ---------------- math helpers (fast MUFU intrinsics, ~1e-7 rel err) ----------------
__device__ __forceinline__ float fast_tanh_half(float z)   // tanh(z/2)
{
    float e = __expf(-fabsf(z));
    float r = __fdividef(1.0f - e, 1.0f + e);
    return copysignf(r, z);
}
__device__ __forceinline__ float two_atanh_clip(float t)   // 2*atanh(clip(t))
{
    t = fminf(fmaxf(t, -0.999999f), 0.999999f);
    return __logf(__fdividef(1.0f + t, 1.0f - t));
}
// Product of nonzero gathered entries; 0 if all zero. Sentinel slots hold 0.
__device__ __forceinline__ float cn_prod8(uint4 q, const float* __restrict__ buf)
{
    int i0 = q.x & 0xffff, i1 = q.x >> 16;
    int i2 = q.y & 0xffff, i3 = q.y >> 16;
    int i4 = q.z & 0xffff, i5 = q.z >> 16;
    int i6 = q.w & 0xffff, i7 = q.w >> 16;
    float p = 1.0f; int any = 0; float v; bool nz;
    v = buf[i0]; nz = (v != 0.0f); any |= nz; p *= nz ? v : 1.0f;
    v = buf[i1]; nz = (v != 0.0f); any |= nz; p *= nz ? v : 1.0f;
    v = buf[i2]; nz = (v != 0.0f); any |= nz; p *= nz ? v : 1.0f;
    v = buf[i3]; nz = (v != 0.0f); any |= nz; p *= nz ? v : 1.0f;
    v = buf[i4]; nz = (v != 0.0f); any |= nz; p *= nz ? v : 1.0f;
    v = buf[i5]; nz = (v != 0.0f); any |= nz; p *= nz ? v : 1.0f;
    v = buf[i6]; nz = (v != 0.0f); any |= nz; p *= nz ? v : 1.0f;
    v = buf[i7]; nz = (v != 0.0f); any |= nz; p *= nz ? v : 1.0f;
    return any ? p : 0.0f;
}

// ---------------- the whole network, fused: one block per batch element ----------------
__global__ void __launch_bounds__(256, 2) bp_main(const float* __restrict__ x,
                                                  float* __restrict__ out)
{
    __shared__ float bufA[HH + 4], bufB[HH + 4], xrow[NN], ybuf[NN + 4];
    const int t = threadIdx.x;
    const int b = blockIdx.x;

    if (t == 0) { bufA[HH] = 0.0f; bufB[HH] = 0.0f; ybuf[NN] = 0.0f; }  // sentinel slots
    for (int n = t; n < NN; n += 256) xrow[n] = x[(size_t)b * NN + n];
    __syncthreads();

    // stage 0: t = tanh(0.5 x) (into ybuf), then h = CN(M_first, t)
    for (int n = t; n < NN; n += 256) ybuf[n] = fast_tanh_half(xrow[n]);
    __syncthreads();
    {
        const uint4* mf = reinterpret_cast<const uint4*>(g_mf_idx);
        for (int i = t; i < HH; i += 256) bufA[i] = cn_prod8(mf[i], ybuf);
    }
    __syncthreads();

    float* hb = bufA;
    float* ub = bufB;
    const uint4*    mc4 = reinterpret_cast<const uint4*>(g_mc_idx);
    const uint2*    wi2 = reinterpret_cast<const uint2*>(g_w_idx);
    const float4*   wv4 = reinterpret_cast<const float4*>(g_w_val);
    const uint32_t* bmi = reinterpret_cast<const uint32_t*>(g_bm_idx);
    const float2*   bmv = reinterpret_cast<const float2*>(g_bm_val);
    const uint32_t* si  = reinterpret_cast<const uint32_t*>(g_s_idx);
    const float2*   sv  = reinterpret_cast<const float2*>(g_s_val);

    for (int l = 0; l < LL; l++) {
        // u = 2*atanh(clip(h));  y = x @ S[l]
        for (int j = t; j < HH; j += 256) ub[j] = two_atanh_clip(hb[j]);
        for (int m = t; m < NN; m += 256) {
            uint32_t q = si[l * NN + m]; float2 w = sv[l * NN + m];
            ybuf[m] = w.x * xrow[q & 0xffff] + w.y * xrow[q >> 16];
        }
        __syncthreads();
        // v = tanh(0.5*(W u + bias_gather(y)))
        for (int i = t; i < HH; i += 256) {
            uint32_t bq = bmi[i]; float2 bw = bmv[i];
            float z = bw.x * ybuf[bq & 0xffff] + bw.y * ybuf[bq >> 16];
            uint2 wq = wi2[l * HH + i]; float4 ww = wv4[l * HH + i];
            z += ww.x * ub[wq.x & 0xffff];
            z += ww.y * ub[wq.x >> 16];
            z += ww.z * ub[wq.y & 0xffff];
            z += ww.w * ub[wq.y >> 16];
            hb[i] = fast_tanh_half(z);
        }
        __syncthreads();
        // h' = CN(M_cn, v)
        for (int i = t; i < HH; i += 256) ub[i] = cn_prod8(mc4[i], hb);
        __syncthreads();
        float* tmp = hb; hb = ub; ub = tmp;
    }

    // output layer
    for (int j = t; j < HH; j += 256) ub[j] = two_atanh_clip(hb[j]);
    for (int m = t; m < NN; m += 256) {
        uint32_t q = si[19 * NN + m]; float2 w = sv[19 * NN + m];
        ybuf[m] = w.x * xrow[q & 0xffff] + w.y * xrow[q >> 16];
    }
    __syncthreads();
    {
        const uint2*    oi2 = reinterpret_cast<const uint2*>(g_wo_idx);
        const float4*   ov4 = reinterpret_cast<const float4*>(g_wo_val);
        const uint32_t* cmi = reinterpret_cast<const uint32_t*>(g_cm_idx);
        const float2*   cmv = reinterpret_cast<const float2*>(g_cm_val);
        for (int n = t; n < NN; n += 256) {
            uint32_t cq = cmi[n]; float2 cw = cmv[n];
            float s = cw.x * ybuf[cq & 0xffff] + cw.y * ybuf[cq >> 16];
            uint2 wq = oi2[n]; float4 ww = ov4[n];
            s += ww.x * ub[wq.x & 0xffff];
            s += ww.y * ub[wq.x >> 16];
            s += ww.z * ub[wq.y & 0xffff];
            s += ww.w * ub[wq.y >> 16];
            out[(size_t)b * NN + n] = __fdividef(1.0f, 1.0f + __expf(-s));
        }
    }
}

// ---------------- launch ----------------
extern "C" void kernel_launch(void* const* d_in, const int* in_sizes, int n_in,
                              void* d_out, int out_size)
{
    (void)in_sizes; (void)n_in; (void)out_size;
    const float* x    = (const float*)d_in[0];   // [256, 768]
    const float* Wvn  = (const float*)d_in[1];   // [19, 3072, 3072]
    const float* Wout = (const float*)d_in[2];   // [768, 3072]
    const float* S    = (const float*)d_in[3];   // [20, 768, 768]
    const float* bm   = (const float*)d_in[4];   // [768, 3072]
    const float* cm   = (const float*)d_in[5];   // [768, 768]
    const float* Mf   = (const float*)d_in[6];   // [3072, 768]
    const float* Mc   = (const float*)d_in[7];   // [3072, 3072]
    float* out = (float*)d_out;                  // [256, 768]

    // Sparsity extraction (8 warps/block -> 8 rows/block for row scans)
    k_wvn <<<(LL * HH + 7) / 8, 256>>>(Wvn);
    k_wout<<<(NN + 7) / 8,      256>>>(Wout);
    k_mf  <<<(HH + 7) / 8,      256>>>(Mf);
    k_mc  <<<(HH + 7) / 8,      256>>>(Mc);
    k_bm  <<<dim3((HH + 255) / 256, 1),  256>>>(bm);
    k_s   <<<dim3((NN + 255) / 256, 20), 256>>>(S);
    k_cm  <<<dim3((NN + 255) / 256, 1),  256>>>(cm);

    // Fused BP network: one block per batch element
    bp_main<<<BB, 256>>>(x, out);
}

// round 14
// speedup vs baseline: 4.2646x; 1.5491x over previous
#include <cuda_runtime.h>
#include <cstdint>

// Problem dims
#define BB 256
#define NN 768
#define HH 3072
#define LL 19

// Fixed CSR/CSC capacities (construction: W_vn<=3, masks<=7, W_out<=4, bm/S/cm cols = 1)
#define CAP_W 4
#define CAP_M 8
#define CAP_O 4
#define CAP_B 2
#define CAP_S 2
#define CAP_C 2

// ---------------- device scratch (no allocation allowed) ----------------
__device__ __align__(16) uint16_t g_w_idx [LL * HH * CAP_W];
__device__ __align__(16) float    g_w_val [LL * HH * CAP_W];
__device__ __align__(16) uint16_t g_mf_idx[HH * CAP_M];
__device__ __align__(16) uint16_t g_mc_idx[HH * CAP_M];
__device__ __align__(16) uint16_t g_wo_idx[NN * CAP_O];
__device__ __align__(16) float    g_wo_val[NN * CAP_O];
__device__ __align__(16) uint16_t g_bm_idx[HH * CAP_B];
__device__ __align__(16) float    g_bm_val[HH * CAP_B];
__device__ __align__(16) uint16_t g_s_idx [20 * NN * CAP_S];
__device__ __align__(16) float    g_s_val [20 * NN * CAP_S];
__device__ __align__(16) uint16_t g_cm_idx[NN * CAP_C];
__device__ __align__(16) float    g_cm_val[NN * CAP_C];

// ---------------- sparsity extraction ----------------
// Warp-per-row, software-pipelined double-buffered batches: batch n+1's loads
// are issued BEFORE batch n is processed, so each warp keeps ~NB LDG.128s
// continuously in flight (no load/drain sawtooth). Fully unrolled -> static
// buffer indices, no register moves. Hits captured per-lane into a tiny
// register list (<=3 / <=7 per whole row); warp compaction once per row.
// Zero test uses bits<<1 so -0.0f counts as zero, matching (x != 0).
template<int C, int CAP, int PCAP, bool ISMASK, int SENT>
__device__ __forceinline__ void row_scan(const float* __restrict__ M, int R, unsigned vb,
                                         uint16_t* __restrict__ idx,
                                         float* __restrict__ val)
{
    int row  = (int)vb * 8 + (threadIdx.x >> 5);
    int lane = threadIdx.x & 31;
    if (row >= R) return;
    const float4* rp = reinterpret_cast<const float4*>(M + (size_t)row * C) + lane;

    int   li[PCAP];
    float lv[PCAP];
    int cnt = 0;

    constexpr int ITER = C / 128;                  // 512B warp-chunks per row (24 or 6)
    constexpr int NB   = 6;                        // pipeline batch size
    static_assert(ITER % NB == 0, "batch must divide row chunks");
    constexpr int NBAT = ITER / NB;                // 4 or 1

    float4 buf[2][NB];
    #pragma unroll
    for (int u = 0; u < NB; u++) buf[0][u] = rp[u * 32];

    #pragma unroll
    for (int bat = 0; bat < NBAT; bat++) {
        // Prefetch next batch before processing current (keeps MLP continuous)
        if (bat + 1 < NBAT) {
            #pragma unroll
            for (int u = 0; u < NB; u++)
                buf[(bat + 1) & 1][u] = rp[((bat + 1) * NB + u) * 32];
        }
        #pragma unroll
        for (int u = 0; u < NB; u++) {
            float4 v = buf[bat & 1][u];
            unsigned a0 = __float_as_uint(v.x) << 1;
            unsigned a1 = __float_as_uint(v.y) << 1;
            unsigned a2 = __float_as_uint(v.z) << 1;
            unsigned a3 = __float_as_uint(v.w) << 1;
            if ((a0 | a1 | a2 | a3) != 0u) {       // per-thread branch, rarely taken
                int col = ((bat * NB + u) * 32 + lane) * 4;
                #pragma unroll
                for (int e = 0; e < 4; e++) {
                    unsigned ae = (e == 0) ? a0 : (e == 1) ? a1 : (e == 2) ? a2 : a3;
                    float    ve = (e == 0) ? v.x : (e == 1) ? v.y : (e == 2) ? v.z : v.w;
                    if (ae != 0u) {
                        #pragma unroll
                        for (int k = 0; k < PCAP; k++)
                            if (cnt == k) { li[k] = col + e; lv[k] = ve; }
                        if (cnt < PCAP) cnt++;
                    }
                }
            }
        }
    }

    // Once-per-row warp compaction
    int pre = cnt;
    #pragma unroll
    for (int d = 1; d < 32; d <<= 1) {
        int o = __shfl_up_sync(0xffffffffu, pre, d);
        if (lane >= d) pre += o;
    }
    int total = __shfl_sync(0xffffffffu, pre, 31);
    int base  = pre - cnt;   // exclusive prefix

    uint16_t* oi = idx + (size_t)row * CAP;
    float*    ov = ISMASK ? nullptr : (val + (size_t)row * CAP);
    #pragma unroll
    for (int k = 0; k < PCAP; k++) {
        if (k < cnt) {
            int p = base + k;
            if (p < CAP) { oi[p] = (uint16_t)li[k]; if (!ISMASK) ov[p] = lv[k]; }
        }
    }
    if (total > CAP) total = CAP;
    for (int p = total + lane; p < CAP; p += 32) {
        oi[p] = (uint16_t)SENT;
        if (!ISMASK) ov[p] = 0.0f;
    }
}

// Thread-per-column scan (reads coalesced across the warp each row step).
template<int CAPT>
__device__ __forceinline__ void col_scan(const float* __restrict__ M, int R, int C,
                                         int col, int sl,
                                         uint16_t* __restrict__ idx, float* __restrict__ val)
{
    if (col >= C) return;
    const float* p = M + (size_t)sl * R * C;
    uint16_t* oi = idx + ((size_t)sl * C + col) * CAPT;
    float*    ov = val + ((size_t)sl * C + col) * CAPT;
    int cnt = 0;
    #pragma unroll 8
    for (int r = 0; r < R; r++) {
        float v = p[(size_t)r * C + col];
        if (v != 0.0f && cnt < CAPT) { oi[cnt] = (uint16_t)r; ov[cnt] = v; cnt++; }
    }
    for (; cnt < CAPT; cnt++) { oi[cnt] = 0; ov[cnt] = 0.0f; }
}

// Merged scan kernel: all seven extractions in one launch. Small scans are in
// the lowest block indices so they dispatch first and hide under the W_vn
// stream instead of trailing it as serialized launch tails.
// Block budget: bm 12 | S 60 | cm 3 | wout 96 | mf 384 | mc 384 | wvn 7296.
#define SCAN_BLOCKS (12 + 60 + 3 + 96 + 384 + 384 + (LL * HH / 8))

__global__ void __launch_bounds__(256) k_scan_all(
    const float* __restrict__ Wvn, const float* __restrict__ Wout,
    const float* __restrict__ Mf,  const float* __restrict__ Mc,
    const float* __restrict__ bm,  const float* __restrict__ S,
    const float* __restrict__ cm)
{
    unsigned vb = blockIdx.x;
    int t = threadIdx.x;
    if (vb < 12) {                       // bias_matrix cols: [768, 3072]
        col_scan<CAP_B>(bm, NN, HH, (int)vb * 256 + t, 0, g_bm_idx, g_bm_val);
        return;
    }
    vb -= 12;
    if (vb < 60) {                       // S cols: 20 x [768, 768], 3 blocks/slice
        col_scan<CAP_S>(S, NN, NN, (int)(vb % 3) * 256 + t, (int)(vb / 3), g_s_idx, g_s_val);
        return;
    }
    vb -= 60;
    if (vb < 3) {                        // channel_mask cols: [768, 768]
        col_scan<CAP_C>(cm, NN, NN, (int)vb * 256 + t, 0, g_cm_idx, g_cm_val);
        return;
    }
    vb -= 3;
    if (vb < 96)  { row_scan<HH, CAP_O, 4, false, 0 >(Wout, NN,    vb, g_wo_idx, g_wo_val); return; }
    vb -= 96;
    if (vb < 384) { row_scan<NN, CAP_M, 8, true,  NN>(Mf,   HH,    vb, g_mf_idx, nullptr);  return; }
    vb -= 384;
    if (vb < 384) { row_scan<HH, CAP_M, 8, true,  HH>(Mc,   HH,    vb, g_mc_idx, nullptr);  return; }
    vb -= 384;
    row_scan<HH, CAP_W, 4, false, 0>(Wvn, LL * HH, vb, g_w_idx, g_w_val);
}

// ---------------- math helpers (fast MUFU intrinsics, ~1e-7 rel err) ----------------
__device__ __forceinline__ float fast_tanh_half(float z)   // tanh(z/2)
{
    float e = __expf(-fabsf(z));
    float r = __fdividef(1.0f - e, 1.0f + e);
    return copysignf(r, z);
}
__device__ __forceinline__ float two_atanh_clip(float t)   // 2*atanh(clip(t))
{
    t = fminf(fmaxf(t, -0.999999f), 0.999999f);
    return __logf(__fdividef(1.0f + t, 1.0f - t));
}
// Product of nonzero gathered entries; 0 if all zero. Sentinel slots hold 0.
__device__ __forceinline__ float cn_prod8(uint4 q, const float* __restrict__ buf)
{
    int i0 = q.x & 0xffff, i1 = q.x >> 16;
    int i2 = q.y & 0xffff, i3 = q.y >> 16;
    int i4 = q.z & 0xffff, i5 = q.z >> 16;
    int i6 = q.w & 0xffff, i7 = q.w >> 16;
    float p = 1.0f; int any = 0; float v; bool nz;
    v = buf[i0]; nz = (v != 0.0f); any |= nz; p *= nz ? v : 1.0f;
    v = buf[i1]; nz = (v != 0.0f); any |= nz; p *= nz ? v : 1.0f;
    v = buf[i2]; nz = (v != 0.0f); any |= nz; p *= nz ? v : 1.0f;
    v = buf[i3]; nz = (v != 0.0f); any |= nz; p *= nz ? v : 1.0f;
    v = buf[i4]; nz = (v != 0.0f); any |= nz; p *= nz ? v : 1.0f;
    v = buf[i5]; nz = (v != 0.0f); any |= nz; p *= nz ? v : 1.0f;
    v = buf[i6]; nz = (v != 0.0f); any |= nz; p *= nz ? v : 1.0f;
    v = buf[i7]; nz = (v != 0.0f); any |= nz; p *= nz ? v : 1.0f;
    return any ? p : 0.0f;
}

// ---------------- the whole network, fused: one block per batch element ----------------
__global__ void __launch_bounds__(256, 2) bp_main(const float* __restrict__ x,
                                                  float* __restrict__ out)
{
    __shared__ float bufA[HH + 4], bufB[HH + 4], xrow[NN], ybuf[NN + 4];
    const int t = threadIdx.x;
    const int b = blockIdx.x;

    if (t == 0) { bufA[HH] = 0.0f; bufB[HH] = 0.0f; ybuf[NN] = 0.0f; }  // sentinel slots
    for (int n = t; n < NN; n += 256) xrow[n] = x[(size_t)b * NN + n];
    __syncthreads();

    // stage 0: t = tanh(0.5 x) (into ybuf), then h = CN(M_first, t)
    for (int n = t; n < NN; n += 256) ybuf[n] = fast_tanh_half(xrow[n]);
    __syncthreads();
    {
        const uint4* mf = reinterpret_cast<const uint4*>(g_mf_idx);
        for (int i = t; i < HH; i += 256) bufA[i] = cn_prod8(mf[i], ybuf);
    }
    __syncthreads();

    float* hb = bufA;
    float* ub = bufB;
    const uint4*    mc4 = reinterpret_cast<const uint4*>(g_mc_idx);
    const uint2*    wi2 = reinterpret_cast<const uint2*>(g_w_idx);
    const float4*   wv4 = reinterpret_cast<const float4*>(g_w_val);
    const uint32_t* bmi = reinterpret_cast<const uint32_t*>(g_bm_idx);
    const float2*   bmv = reinterpret_cast<const float2*>(g_bm_val);
    const uint32_t* si  = reinterpret_cast<const uint32_t*>(g_s_idx);
    const float2*   sv  = reinterpret_cast<const float2*>(g_s_val);

    for (int l = 0; l < LL; l++) {
        // u = 2*atanh(clip(h));  y = x @ S[l]
        for (int j = t; j < HH; j += 256) ub[j] = two_atanh_clip(hb[j]);
        for (int m = t; m < NN; m += 256) {
            uint32_t q = si[l * NN + m]; float2 w = sv[l * NN + m];
            ybuf[m] = w.x * xrow[q & 0xffff] + w.y * xrow[q >> 16];
        }
        __syncthreads();
        // v = tanh(0.5*(W u + bias_gather(y)))
        for (int i = t; i < HH; i += 256) {
            uint32_t bq = bmi[i]; float2 bw = bmv[i];
            float z = bw.x * ybuf[bq & 0xffff] + bw.y * ybuf[bq >> 16];
            uint2 wq = wi2[l * HH + i]; float4 ww = wv4[l * HH + i];
            z += ww.x * ub[wq.x & 0xffff];
            z += ww.y * ub[wq.x >> 16];
            z += ww.z * ub[wq.y & 0xffff];
            z += ww.w * ub[wq.y >> 16];
            hb[i] = fast_tanh_half(z);
        }
        __syncthreads();
        // h' = CN(M_cn, v)
        for (int i = t; i < HH; i += 256) ub[i] = cn_prod8(mc4[i], hb);
        __syncthreads();
        float* tmp = hb; hb = ub; ub = tmp;
    }

    // output layer
    for (int j = t; j < HH; j += 256) ub[j] = two_atanh_clip(hb[j]);
    for (int m = t; m < NN; m += 256) {
        uint32_t q = si[19 * NN + m]; float2 w = sv[19 * NN + m];
        ybuf[m] = w.x * xrow[q & 0xffff] + w.y * xrow[q >> 16];
    }
    __syncthreads();
    {
        const uint2*    oi2 = reinterpret_cast<const uint2*>(g_wo_idx);
        const float4*   ov4 = reinterpret_cast<const float4*>(g_wo_val);
        const uint32_t* cmi = reinterpret_cast<const uint32_t*>(g_cm_idx);
        const float2*   cmv = reinterpret_cast<const float2*>(g_cm_val);
        for (int n = t; n < NN; n += 256) {
            uint32_t cq = cmi[n]; float2 cw = cmv[n];
            float s = cw.x * ybuf[cq & 0xffff] + cw.y * ybuf[cq >> 16];
            uint2 wq = oi2[n]; float4 ww = ov4[n];
            s += ww.x * ub[wq.x & 0xffff];
            s += ww.y * ub[wq.x >> 16];
            s += ww.z * ub[wq.y & 0xffff];
            s += ww.w * ub[wq.y >> 16];
            out[(size_t)b * NN + n] = __fdividef(1.0f, 1.0f + __expf(-s));
        }
    }
}

// ---------------- launch ----------------
extern "C" void kernel_launch(void* const* d_in, const int* in_sizes, int n_in,
                              void* d_out, int out_size)
{
    (void)in_sizes; (void)n_in; (void)out_size;
    const float* x    = (const float*)d_in[0];   // [256, 768]
    const float* Wvn  = (const float*)d_in[1];   // [19, 3072, 3072]
    const float* Wout = (const float*)d_in[2];   // [768, 3072]
    const float* S    = (const float*)d_in[3];   // [20, 768, 768]
    const float* bm   = (const float*)d_in[4];   // [768, 3072]
    const float* cm   = (const float*)d_in[5];   // [768, 768]
    const float* Mf   = (const float*)d_in[6];   // [3072, 768]
    const float* Mc   = (const float*)d_in[7];   // [3072, 3072]
    float* out = (float*)d_out;                  // [256, 768]

    // One merged extraction launch (small scans dispatch first, hide under W_vn)
    k_scan_all<<<SCAN_BLOCKS, 256>>>(Wvn, Wout, Mf, Mc, bm, S, cm);

    // Fused BP network: one block per batch element
    bp_main<<<BB, 256>>>(x, out);
}

// round 16
// speedup vs baseline: 5.1670x; 1.2116x over previous
#include <cuda_runtime.h>
#include <cstdint>

// Problem dims
#define BB 256
#define NN 768
#define HH 3072
#define LL 19

// Fixed CSR/CSC capacities (construction: W_vn<=3, masks<=7, W_out<=4, bm/S/cm cols = 1)
#define CAP_W 4
#define CAP_M 8
#define CAP_O 4
#define CAP_B 2
#define CAP_S 2
#define CAP_C 2

// ---------------- device scratch (no allocation allowed) ----------------
__device__ __align__(16) uint16_t g_w_idx [LL * HH * CAP_W];
__device__ __align__(16) float    g_w_val [LL * HH * CAP_W];
__device__ __align__(16) uint16_t g_mf_idx[HH * CAP_M];
__device__ __align__(16) uint16_t g_mc_idx[HH * CAP_M];
__device__ __align__(16) uint16_t g_wo_idx[NN * CAP_O];
__device__ __align__(16) float    g_wo_val[NN * CAP_O];
__device__ __align__(16) uint16_t g_bm_idx[HH * CAP_B];
__device__ __align__(16) float    g_bm_val[HH * CAP_B];
__device__ __align__(16) uint16_t g_s_idx [20 * NN * CAP_S];
__device__ __align__(16) float    g_s_val [20 * NN * CAP_S];
__device__ __align__(16) uint16_t g_cm_idx[NN * CAP_C];
__device__ __align__(16) float    g_cm_val[NN * CAP_C];

// ---------------- sparsity extraction (unchanged from R14 — near LTS cap) ----------------
// Warp-per-row, software-pipelined double-buffered batches.
template<int C, int CAP, int PCAP, bool ISMASK, int SENT>
__device__ __forceinline__ void row_scan(const float* __restrict__ M, int R, unsigned vb,
                                         uint16_t* __restrict__ idx,
                                         float* __restrict__ val)
{
    int row  = (int)vb * 8 + (threadIdx.x >> 5);
    int lane = threadIdx.x & 31;
    if (row >= R) return;
    const float4* rp = reinterpret_cast<const float4*>(M + (size_t)row * C) + lane;

    int   li[PCAP];
    float lv[PCAP];
    int cnt = 0;

    constexpr int ITER = C / 128;                  // 512B warp-chunks per row (24 or 6)
    constexpr int NB   = 6;                        // pipeline batch size
    static_assert(ITER % NB == 0, "batch must divide row chunks");
    constexpr int NBAT = ITER / NB;                // 4 or 1

    float4 buf[2][NB];
    #pragma unroll
    for (int u = 0; u < NB; u++) buf[0][u] = rp[u * 32];

    #pragma unroll
    for (int bat = 0; bat < NBAT; bat++) {
        if (bat + 1 < NBAT) {
            #pragma unroll
            for (int u = 0; u < NB; u++)
                buf[(bat + 1) & 1][u] = rp[((bat + 1) * NB + u) * 32];
        }
        #pragma unroll
        for (int u = 0; u < NB; u++) {
            float4 v = buf[bat & 1][u];
            unsigned a0 = __float_as_uint(v.x) << 1;
            unsigned a1 = __float_as_uint(v.y) << 1;
            unsigned a2 = __float_as_uint(v.z) << 1;
            unsigned a3 = __float_as_uint(v.w) << 1;
            if ((a0 | a1 | a2 | a3) != 0u) {       // per-thread branch, rarely taken
                int col = ((bat * NB + u) * 32 + lane) * 4;
                #pragma unroll
                for (int e = 0; e < 4; e++) {
                    unsigned ae = (e == 0) ? a0 : (e == 1) ? a1 : (e == 2) ? a2 : a3;
                    float    ve = (e == 0) ? v.x : (e == 1) ? v.y : (e == 2) ? v.z : v.w;
                    if (ae != 0u) {
                        #pragma unroll
                        for (int k = 0; k < PCAP; k++)
                            if (cnt == k) { li[k] = col + e; lv[k] = ve; }
                        if (cnt < PCAP) cnt++;
                    }
                }
            }
        }
    }

    int pre = cnt;
    #pragma unroll
    for (int d = 1; d < 32; d <<= 1) {
        int o = __shfl_up_sync(0xffffffffu, pre, d);
        if (lane >= d) pre += o;
    }
    int total = __shfl_sync(0xffffffffu, pre, 31);
    int base  = pre - cnt;

    uint16_t* oi = idx + (size_t)row * CAP;
    float*    ov = ISMASK ? nullptr : (val + (size_t)row * CAP);
    #pragma unroll
    for (int k = 0; k < PCAP; k++) {
        if (k < cnt) {
            int p = base + k;
            if (p < CAP) { oi[p] = (uint16_t)li[k]; if (!ISMASK) ov[p] = lv[k]; }
        }
    }
    if (total > CAP) total = CAP;
    for (int p = total + lane; p < CAP; p += 32) {
        oi[p] = (uint16_t)SENT;
        if (!ISMASK) ov[p] = 0.0f;
    }
}

template<int CAPT>
__device__ __forceinline__ void col_scan(const float* __restrict__ M, int R, int C,
                                         int col, int sl,
                                         uint16_t* __restrict__ idx, float* __restrict__ val)
{
    if (col >= C) return;
    const float* p = M + (size_t)sl * R * C;
    uint16_t* oi = idx + ((size_t)sl * C + col) * CAPT;
    float*    ov = val + ((size_t)sl * C + col) * CAPT;
    int cnt = 0;
    #pragma unroll 8
    for (int r = 0; r < R; r++) {
        float v = p[(size_t)r * C + col];
        if (v != 0.0f && cnt < CAPT) { oi[cnt] = (uint16_t)r; ov[cnt] = v; cnt++; }
    }
    for (; cnt < CAPT; cnt++) { oi[cnt] = 0; ov[cnt] = 0.0f; }
}

// Merged scan: small scans first so they hide under the W_vn stream.
#define SCAN_BLOCKS (12 + 60 + 3 + 96 + 384 + 384 + (LL * HH / 8))

__global__ void __launch_bounds__(256) k_scan_all(
    const float* __restrict__ Wvn, const float* __restrict__ Wout,
    const float* __restrict__ Mf,  const float* __restrict__ Mc,
    const float* __restrict__ bm,  const float* __restrict__ S,
    const float* __restrict__ cm)
{
    unsigned vb = blockIdx.x;
    int t = threadIdx.x;
    if (vb < 12) { col_scan<CAP_B>(bm, NN, HH, (int)vb * 256 + t, 0, g_bm_idx, g_bm_val); return; }
    vb -= 12;
    if (vb < 60) { col_scan<CAP_S>(S, NN, NN, (int)(vb % 3) * 256 + t, (int)(vb / 3), g_s_idx, g_s_val); return; }
    vb -= 60;
    if (vb < 3)  { col_scan<CAP_C>(cm, NN, NN, (int)vb * 256 + t, 0, g_cm_idx, g_cm_val); return; }
    vb -= 3;
    if (vb < 96)  { row_scan<HH, CAP_O, 4, false, 0 >(Wout, NN,    vb, g_wo_idx, g_wo_val); return; }
    vb -= 96;
    if (vb < 384) { row_scan<NN, CAP_M, 8, true,  NN>(Mf,   HH,    vb, g_mf_idx, nullptr);  return; }
    vb -= 384;
    if (vb < 384) { row_scan<HH, CAP_M, 8, true,  HH>(Mc,   HH,    vb, g_mc_idx, nullptr);  return; }
    vb -= 384;
    row_scan<HH, CAP_W, 4, false, 0>(Wvn, LL * HH, vb, g_w_idx, g_w_val);
}

// ---------------- math helpers (fast MUFU intrinsics, ~1e-7 rel err) ----------------
__device__ __forceinline__ float fast_tanh_half(float z)   // tanh(z/2)
{
    float e = __expf(-fabsf(z));
    float r = __fdividef(1.0f - e, 1.0f + e);
    return copysignf(r, z);
}
__device__ __forceinline__ float two_atanh_clip(float t)   // 2*atanh(clip(t))
{
    t = fminf(fmaxf(t, -0.999999f), 0.999999f);
    return __logf(__fdividef(1.0f + t, 1.0f - t));
}
// 2*atanh(clip( product of nonzero gathered entries )); product=0 if all zero.
// Sentinel-padded indices point to a guaranteed-0 slot => skipped like zeros.
__device__ __forceinline__ float cn_atanh8(uint4 q, const float* __restrict__ buf)
{
    int i0 = q.x & 0xffff, i1 = q.x >> 16;
    int i2 = q.y & 0xffff, i3 = q.y >> 16;
    int i4 = q.z & 0xffff, i5 = q.z >> 16;
    int i6 = q.w & 0xffff, i7 = q.w >> 16;
    float p = 1.0f; int any = 0; float v; bool nz;
    v = buf[i0]; nz = (v != 0.0f); any |= nz; p *= nz ? v : 1.0f;
    v = buf[i1]; nz = (v != 0.0f); any |= nz; p *= nz ? v : 1.0f;
    v = buf[i2]; nz = (v != 0.0f); any |= nz; p *= nz ? v : 1.0f;
    v = buf[i3]; nz = (v != 0.0f); any |= nz; p *= nz ? v : 1.0f;
    v = buf[i4]; nz = (v != 0.0f); any |= nz; p *= nz ? v : 1.0f;
    v = buf[i5]; nz = (v != 0.0f); any |= nz; p *= nz ? v : 1.0f;
    v = buf[i6]; nz = (v != 0.0f); any |= nz; p *= nz ? v : 1.0f;
    v = buf[i7]; nz = (v != 0.0f); any |= nz; p *= nz ? v : 1.0f;
    float c = any ? p : 0.0f;
    return two_atanh_clip(c);     // every CN output is only ever consumed via 2*atanh(clip(.))
}

// ---------------- the whole network, fused: one block per batch element ----------------
// 512 threads (16 warps) for LDS-latency hiding; 2 HH-passes + 2 bars per layer
// (atanh fused into the CN stage; y=S_l bias row computed in the prior stage,
// since it depends only on the layer-invariant xrow).
#define TPB 512

__global__ void __launch_bounds__(TPB, 2) bp_main(const float* __restrict__ x,
                                                  float* __restrict__ out)
{
    __shared__ float vbuf[HH + 4];      // v (tanh outputs); sentinel at [HH]
    __shared__ float ubuf[HH];          // u = 2*atanh(clip(CN(...)))
    __shared__ float xrow[NN];
    __shared__ float tnh[NN + 4];       // tanh(x/2); sentinel at [NN]
    __shared__ float ybuf[NN];          // current layer's (x@S_l) row

    const int t = threadIdx.x;
    const int b = blockIdx.x;

    if (t == 0) { vbuf[HH] = 0.0f; tnh[NN] = 0.0f; }
    for (int n = t; n < NN; n += TPB) xrow[n] = x[(size_t)b * NN + n];
    __syncthreads();
    for (int n = t; n < NN; n += TPB) tnh[n] = fast_tanh_half(xrow[n]);
    __syncthreads();

    const uint4*    mf4 = reinterpret_cast<const uint4*>(g_mf_idx);
    const uint4*    mc4 = reinterpret_cast<const uint4*>(g_mc_idx);
    const uint2*    wi2 = reinterpret_cast<const uint2*>(g_w_idx);
    const float4*   wv4 = reinterpret_cast<const float4*>(g_w_val);
    const uint32_t* bmi = reinterpret_cast<const uint32_t*>(g_bm_idx);
    const float2*   bmv = reinterpret_cast<const float2*>(g_bm_val);
    const uint32_t* si  = reinterpret_cast<const uint32_t*>(g_s_idx);
    const float2*   sv  = reinterpret_cast<const float2*>(g_s_val);

    // stage 0: u = atanh(CN(M_first, tanh(x/2)));  y = x @ S[0]
    for (int i = t; i < HH; i += TPB) ubuf[i] = cn_atanh8(mf4[i], tnh);
    for (int m = t; m < NN; m += TPB) {
        uint32_t q = si[m]; float2 w = sv[m];
        ybuf[m] = w.x * xrow[q & 0xffff] + w.y * xrow[q >> 16];
    }
    __syncthreads();

    for (int l = 0; l < LL; l++) {
        // stage 1: v = tanh(0.5*(W_l u + bias_gather(y_l)))
        for (int i = t; i < HH; i += TPB) {
            uint32_t bq = bmi[i]; float2 bw = bmv[i];
            float z = bw.x * ybuf[bq & 0xffff] + bw.y * ybuf[bq >> 16];
            uint2 wq = wi2[l * HH + i]; float4 ww = wv4[l * HH + i];
            z += ww.x * ubuf[wq.x & 0xffff];
            z += ww.y * ubuf[wq.x >> 16];
            z += ww.z * ubuf[wq.y & 0xffff];
            z += ww.w * ubuf[wq.y >> 16];
            vbuf[i] = fast_tanh_half(z);
        }
        __syncthreads();
        // stage 2: u' = atanh(CN(M_cn, v));  y_{l+1} = x @ S[l+1]
        for (int i = t; i < HH; i += TPB) ubuf[i] = cn_atanh8(mc4[i], vbuf);
        for (int m = t; m < NN; m += TPB) {
            uint32_t q = si[(l + 1) * NN + m]; float2 w = sv[(l + 1) * NN + m];
            ybuf[m] = w.x * xrow[q & 0xffff] + w.y * xrow[q >> 16];
        }
        __syncthreads();
    }

    // output: sigmoid(W_out u + channel_mask_gather(y_19))
    {
        const uint2*    oi2 = reinterpret_cast<const uint2*>(g_wo_idx);
        const float4*   ov4 = reinterpret_cast<const float4*>(g_wo_val);
        const uint32_t* cmi = reinterpret_cast<const uint32_t*>(g_cm_idx);
        const float2*   cmv = reinterpret_cast<const float2*>(g_cm_val);
        for (int n = t; n < NN; n += TPB) {
            uint32_t cq = cmi[n]; float2 cw = cmv[n];
            float s = cw.x * ybuf[cq & 0xffff] + cw.y * ybuf[cq >> 16];
            uint2 wq = oi2[n]; float4 ww = ov4[n];
            s += ww.x * ubuf[wq.x & 0xffff];
            s += ww.y * ubuf[wq.x >> 16];
            s += ww.z * ubuf[wq.y & 0xffff];
            s += ww.w * ubuf[wq.y >> 16];
            out[(size_t)b * NN + n] = __fdividef(1.0f, 1.0f + __expf(-s));
        }
    }
}

// ---------------- launch ----------------
extern "C" void kernel_launch(void* const* d_in, const int* in_sizes, int n_in,
                              void* d_out, int out_size)
{
    (void)in_sizes; (void)n_in; (void)out_size;
    const float* x    = (const float*)d_in[0];   // [256, 768]
    const float* Wvn  = (const float*)d_in[1];   // [19, 3072, 3072]
    const float* Wout = (const float*)d_in[2];   // [768, 3072]
    const float* S    = (const float*)d_in[3];   // [20, 768, 768]
    const float* bm   = (const float*)d_in[4];   // [768, 3072]
    const float* cm   = (const float*)d_in[5];   // [768, 768]
    const float* Mf   = (const float*)d_in[6];   // [3072, 768]
    const float* Mc   = (const float*)d_in[7];   // [3072, 3072]
    float* out = (float*)d_out;                  // [256, 768]

    // One merged extraction launch (small scans dispatch first, hide under W_vn)
    k_scan_all<<<SCAN_BLOCKS, 256>>>(Wvn, Wout, Mf, Mc, bm, S, cm);

    // Fused BP network: one block per batch element
    bp_main<<<BB, TPB>>>(x, out);
}